// round 1
// baseline (speedup 1.0000x reference)
#include <cuda_runtime.h>
#include <cstdint>
#include <cstddef>

#define TSTEPS 256
#define NB     64
#define HID    512
#define G4     2048
#define MROWS  (TSTEPS * NB)   // 16384
#define D2H    1024

// ---------------- scratch (device globals; no allocation allowed) ----------------
__device__ float g_gf[(size_t)MROWS * G4];     // fwd gate pre-activations [T,B,4H]
__device__ float g_gb[(size_t)MROWS * G4];     // bwd gate pre-activations
__device__ float g_feat0[(size_t)MROWS * D2H]; // layer0 output
__device__ float g_feat1[(size_t)MROWS * D2H]; // layer1 highway output
__device__ float g_lstm[(size_t)MROWS * D2H];  // raw bilstm out for layers 1,2
__device__ float g_h[2][2][NB * HID];          // [dir][pingpong][B*H]
__device__ unsigned g_barc = 0;
__device__ volatile unsigned g_barg = 0;

__device__ __forceinline__ float sigmoidf_(float x) { return 1.f / (1.f + __expf(-x)); }

// sense-reversing grid barrier across exactly 128 resident blocks
__device__ __forceinline__ void grid_barrier_128() {
    __syncthreads();
    if (threadIdx.x == 0) {
        __threadfence();
        unsigned gen = g_barg;              // read BEFORE add (prevents lost-wakeup)
        unsigned a = atomicAdd(&g_barc, 1u);
        if (a == 127u) {
            g_barc = 0u;
            __threadfence();
            g_barg = gen + 1u;
        } else {
            while (g_barg == gen) { }
            __threadfence();
        }
    }
    __syncthreads();
}

// ---------------- GEMM: gates = A[M,K] @ W[N,K]^T + bias, N=2048, M=16384 ---------
// grid: (N/128, M/128, 2) ; z selects direction (f/b weights+bias+output)
__global__ __launch_bounds__(256) void gemm_gates(
    const float* __restrict__ A,
    const float* __restrict__ Wf, const float* __restrict__ Wb,
    const float* __restrict__ bf, const float* __restrict__ bb,
    int K)
{
    __shared__ float As[8][128];
    __shared__ float Bs[8][128];
    const float* W    = blockIdx.z ? Wb : Wf;
    const float* bias = blockIdx.z ? bb : bf;
    float*       C    = blockIdx.z ? g_gb : g_gf;

    const int bm = blockIdx.y * 128;
    const int bn = blockIdx.x * 128;
    const int tid = threadIdx.x;
    const int tm = (tid >> 4) * 8;
    const int tn = (tid & 15) * 8;
    const int lr = tid >> 1;
    const int lk = (tid & 1) * 4;

    float acc[8][8];
#pragma unroll
    for (int i = 0; i < 8; i++)
#pragma unroll
        for (int j = 0; j < 8; j++) acc[i][j] = 0.f;

    const float* Ap = A + (size_t)(bm + lr) * K + lk;
    const float* Wp = W + (size_t)(bn + lr) * K + lk;

    for (int k0 = 0; k0 < K; k0 += 8) {
        float4 av = *(const float4*)(Ap + k0);
        float4 wv = *(const float4*)(Wp + k0);
        __syncthreads();
        As[lk + 0][lr] = av.x; As[lk + 1][lr] = av.y;
        As[lk + 2][lr] = av.z; As[lk + 3][lr] = av.w;
        Bs[lk + 0][lr] = wv.x; Bs[lk + 1][lr] = wv.y;
        Bs[lk + 2][lr] = wv.z; Bs[lk + 3][lr] = wv.w;
        __syncthreads();
#pragma unroll
        for (int k = 0; k < 8; k++) {
            float ar[8], br[8];
#pragma unroll
            for (int i = 0; i < 8; i++) ar[i] = As[k][tm + i];
#pragma unroll
            for (int j = 0; j < 8; j++) br[j] = Bs[k][tn + j];
#pragma unroll
            for (int i = 0; i < 8; i++)
#pragma unroll
                for (int j = 0; j < 8; j++) acc[i][j] += ar[i] * br[j];
        }
    }
#pragma unroll
    for (int i = 0; i < 8; i++) {
        size_t ro = (size_t)(bm + tm + i) * G4 + bn + tn;
#pragma unroll
        for (int j = 0; j < 8; j++)
            C[ro + j] = acc[i][j] + bias[bn + tn + j];
    }
}

// ---------------- highway projection: g=sigmoid(A@W^T+b); dst=g*A+(1-g)*prev -----
// M=16384, N=K=1024.  grid: (8, 128)
__global__ __launch_bounds__(256) void proj_highway(
    const float* __restrict__ A,
    const float* __restrict__ W,
    const float* __restrict__ bias,
    const float* __restrict__ prev,
    float* __restrict__ dst)
{
    const int K = 1024, N = 1024;
    __shared__ float As[8][128];
    __shared__ float Bs[8][128];
    const int bm = blockIdx.y * 128;
    const int bn = blockIdx.x * 128;
    const int tid = threadIdx.x;
    const int tm = (tid >> 4) * 8;
    const int tn = (tid & 15) * 8;
    const int lr = tid >> 1;
    const int lk = (tid & 1) * 4;

    float acc[8][8];
#pragma unroll
    for (int i = 0; i < 8; i++)
#pragma unroll
        for (int j = 0; j < 8; j++) acc[i][j] = 0.f;

    const float* Ap = A + (size_t)(bm + lr) * K + lk;
    const float* Wp = W + (size_t)(bn + lr) * K + lk;

    for (int k0 = 0; k0 < K; k0 += 8) {
        float4 av = *(const float4*)(Ap + k0);
        float4 wv = *(const float4*)(Wp + k0);
        __syncthreads();
        As[lk + 0][lr] = av.x; As[lk + 1][lr] = av.y;
        As[lk + 2][lr] = av.z; As[lk + 3][lr] = av.w;
        Bs[lk + 0][lr] = wv.x; Bs[lk + 1][lr] = wv.y;
        Bs[lk + 2][lr] = wv.z; Bs[lk + 3][lr] = wv.w;
        __syncthreads();
#pragma unroll
        for (int k = 0; k < 8; k++) {
            float ar[8], br[8];
#pragma unroll
            for (int i = 0; i < 8; i++) ar[i] = As[k][tm + i];
#pragma unroll
            for (int j = 0; j < 8; j++) br[j] = Bs[k][tn + j];
#pragma unroll
            for (int i = 0; i < 8; i++)
#pragma unroll
                for (int j = 0; j < 8; j++) acc[i][j] += ar[i] * br[j];
        }
    }
#pragma unroll
    for (int i = 0; i < 8; i++) {
        int row = bm + tm + i;
#pragma unroll
        for (int j = 0; j < 8; j++) {
            int col = bn + tn + j;
            float z = acc[i][j] + bias[col];
            float g = sigmoidf_(z);
            size_t idx = (size_t)row * N + col;
            dst[idx] = g * A[idx] + (1.f - g) * prev[idx];
        }
    }
}

// ---------------- persistent recurrent kernel -------------------------------------
// 128 blocks (64/dir), 128 threads. Block owns 8 hidden units (all 4 gates, all 64
// batches). Whh slice (32 rows x 512) staged once in shared, reused for 256 steps.
#define SM_WS (512 * 33)
#define SM_HS (64 * 65)
#define SMEM_REC ((SM_WS + SM_HS) * sizeof(float))

__global__ __launch_bounds__(128, 1) void lstm_rec(
    const float* __restrict__ Whh_f, const float* __restrict__ Whh_b,
    const float* __restrict__ init_f, const float* __restrict__ init_b,
    const float* __restrict__ masks,
    float* __restrict__ outbuf,   // [T,B,2H]; this dir writes cols [dir*H, dir*H+H)
    float* __restrict__ hn, float* __restrict__ cn,  // [6,B,H]
    int layer)
{
    extern __shared__ float sm[];
    float* Ws = sm;           // [512][33] transposed Whh slice (k-major, padded)
    float* hs = sm + SM_WS;   // [64][65]  h tile (batch-major, padded)

    const int dir = blockIdx.x >> 6;
    const int hb  = (blockIdx.x & 63) << 3;          // hidden base (8 units)
    const float* gbuf = dir ? g_gb : g_gf;
    const float* Whh  = dir ? Whh_b : Whh_f;
    const float* init = dir ? init_b : init_f;       // [2,512]: h0 then c0
    const int tid = threadIdx.x;
    const int hid = tid & 7;                         // local hidden unit
    const int b0  = (tid >> 3) << 2;                 // batch base (4 batches)
    const int hg  = hb + hid;                        // global hidden idx

    // stage weights: Ws[k][g*8+j] = Whh[g*512 + hb + j][k]
    for (int i = tid; i < 32 * 512; i += 128) {
        int c = i >> 9;            // 0..31
        int k = i & 511;
        int grow = ((c >> 3) << 9) + hb + (c & 7);
        Ws[k * 33 + c] = Whh[(size_t)grow * 512 + k];
    }

    float cst[4], hlast[4];
    {
        float c0 = init[512 + hg];
#pragma unroll
        for (int b = 0; b < 4; b++) { cst[b] = c0; hlast[b] = 0.f; }
    }
    __syncthreads();

    for (int t = 0; t < TSTEPS; ++t) {
        const int tg = dir ? (TSTEPS - 1 - t) : t;

        float ai[4], af[4], ag[4], ao[4];
        const float* gp = gbuf + (size_t)tg * NB * G4 + hg;
#pragma unroll
        for (int b = 0; b < 4; b++) {
            const float* r = gp + (size_t)(b0 + b) * G4;
            ai[b] = r[0]; af[b] = r[512]; ag[b] = r[1024]; ao[b] = r[1536];
        }

        const float* hsrc = &g_h[dir][(t + 1) & 1][0];  // (t-1)&1
        for (int k0 = 0; k0 < 512; k0 += 64) {
            __syncthreads();   // protect hs from previous tile's readers
            if (t == 0) {
                for (int i = tid; i < 64 * 64; i += 128) {
                    int bb = i >> 6, kk = i & 63;
                    hs[bb * 65 + kk] = init[k0 + kk];    // h0 broadcast over batch
                }
            } else {
                for (int i = tid; i < 64 * 64; i += 128) {
                    int bb = i >> 6, kk = i & 63;
                    hs[bb * 65 + kk] = hsrc[bb * 512 + k0 + kk];
                }
            }
            __syncthreads();
#pragma unroll 8
            for (int kk = 0; kk < 64; kk++) {
                const float* wrow = &Ws[(k0 + kk) * 33 + hid];
                float wi = wrow[0], wf = wrow[8], wg = wrow[16], wo = wrow[24];
#pragma unroll
                for (int b = 0; b < 4; b++) {
                    float hv = hs[(b0 + b) * 65 + kk];
                    ai[b] += hv * wi; af[b] += hv * wf;
                    ag[b] += hv * wg; ao[b] += hv * wo;
                }
            }
        }

        float* hdst = &g_h[dir][t & 1][0];
        float* od = outbuf + (size_t)tg * NB * D2H + dir * HID + hg;
#pragma unroll
        for (int b = 0; b < 4; b++) {
            float m = masks[tg * NB + b0 + b];
            float I = sigmoidf_(ai[b]);
            float F = sigmoidf_(af[b]);
            float Gv = tanhf(ag[b]);
            float O = sigmoidf_(ao[b]);
            float c = (F * cst[b] + I * Gv) * m;
            cst[b] = c;
            float h = O * tanhf(c) * m;
            hlast[b] = h;
            hdst[(b0 + b) * HID + hg] = h;
            od[(size_t)(b0 + b) * D2H] = h;
        }
        grid_barrier_128();
    }

    const int si = layer * 2 + dir;   // h_n order: fh0, bh0, fh1, bh1, fh2, bh2
#pragma unroll
    for (int b = 0; b < 4; b++) {
        hn[(size_t)si * NB * HID + (b0 + b) * HID + hg] = hlast[b];
        cn[(size_t)si * NB * HID + (b0 + b) * HID + hg] = cst[b];
    }
}

// ---------------- host ------------------------------------------------------------
extern "C" void kernel_launch(void* const* d_in, const int* in_sizes, int n_in,
                              void* d_out, int out_size)
{
    const float* x     = (const float*)d_in[0];   // [256,64,512]
    const float* masks = (const float*)d_in[1];   // [256,64,1]
    const float* fWih0 = (const float*)d_in[2];   // [2048,512]
    const float* fWihR = (const float*)d_in[3];   // [2,2048,1024]
    const float* fWhh  = (const float*)d_in[4];   // [3,2048,512]
    const float* fb    = (const float*)d_in[5];   // [3,2048]
    const float* bWih0 = (const float*)d_in[6];
    const float* bWihR = (const float*)d_in[7];
    const float* bWhh  = (const float*)d_in[8];
    const float* bb    = (const float*)d_in[9];
    const float* finit = (const float*)d_in[10];  // [3,2,512]
    const float* binit = (const float*)d_in[11];
    const float* projW = (const float*)d_in[12];  // [2,1024,1024]
    const float* projB = (const float*)d_in[13];  // [2,1024]

    float* out = (float*)d_out;                      // [256,64,1024]
    float* hn  = out + (size_t)MROWS * D2H;          // [6,64,512]
    float* cn  = hn + (size_t)6 * NB * HID;          // [6,64,512]

    float *feat0, *feat1, *lstmb;
    cudaGetSymbolAddress((void**)&feat0, g_feat0);
    cudaGetSymbolAddress((void**)&feat1, g_feat1);
    cudaGetSymbolAddress((void**)&lstmb, g_lstm);

    cudaFuncSetAttribute(lstm_rec, cudaFuncAttributeMaxDynamicSharedMemorySize,
                         (int)SMEM_REC);

    dim3 gg(G4 / 128, MROWS / 128, 2);
    dim3 gp(1024 / 128, MROWS / 128, 1);

    // ---- layer 0 (K = 512, input = x) ----
    gemm_gates<<<gg, 256>>>(x, fWih0, bWih0, fb, bb, 512);
    lstm_rec<<<128, 128, SMEM_REC>>>(fWhh, bWhh, finit, binit, masks,
                                     feat0, hn, cn, 0);

    // ---- layer 1 (K = 1024, input = feat0) ----
    gemm_gates<<<gg, 256>>>(feat0, fWihR, bWihR, fb + 2048, bb + 2048, 1024);
    lstm_rec<<<128, 128, SMEM_REC>>>(fWhh + (size_t)2048 * 512,
                                     bWhh + (size_t)2048 * 512,
                                     finit + 1024, binit + 1024, masks,
                                     lstmb, hn, cn, 1);
    proj_highway<<<gp, 256>>>(lstmb, projW, projB, feat0, feat1);

    // ---- layer 2 (K = 1024, input = feat1) ----
    gemm_gates<<<gg, 256>>>(feat1, fWihR + (size_t)2048 * 1024,
                            bWihR + (size_t)2048 * 1024,
                            fb + 4096, bb + 4096, 1024);
    lstm_rec<<<128, 128, SMEM_REC>>>(fWhh + (size_t)2 * 2048 * 512,
                                     bWhh + (size_t)2 * 2048 * 512,
                                     finit + 2048, binit + 2048, masks,
                                     lstmb, hn, cn, 2);
    proj_highway<<<gp, 256>>>(lstmb, projW + (size_t)1024 * 1024, projB + 1024,
                              feat1, out);
}

// round 2
// speedup vs baseline: 1.1906x; 1.1906x over previous
#include <cuda_runtime.h>
#include <cstdint>
#include <cstddef>

#define TSTEPS 256
#define NB     64
#define HID    512
#define G4     2048
#define MROWS  (TSTEPS * NB)   // 16384
#define D2H    1024

// ---------------- scratch (device globals; no allocation allowed) ----------------
__device__ float g_gf[(size_t)MROWS * G4];     // fwd gate pre-activations [T,B,4H]
__device__ float g_gb[(size_t)MROWS * G4];     // bwd gate pre-activations
__device__ float g_feat0[(size_t)MROWS * D2H]; // layer0 output
__device__ float g_feat1[(size_t)MROWS * D2H]; // layer1 highway output
__device__ float g_lstm[(size_t)MROWS * D2H];  // raw bilstm out for layers 1,2
__device__ float g_h[2][2][NB * HID];          // [dir][pingpong][B*H]
__device__ unsigned g_barc2[2];
__device__ volatile unsigned g_barg2[2];

__device__ __forceinline__ float sigmoidf_(float x) { return 1.f / (1.f + __expf(-x)); }

// sense-reversing grid barrier across 64 blocks of one direction
__device__ __forceinline__ void grid_barrier_dir(int dir) {
    __syncthreads();
    if (threadIdx.x == 0) {
        __threadfence();
        unsigned gen = g_barg2[dir];
        unsigned a = atomicAdd(&g_barc2[dir], 1u);
        if (a == 63u) {
            g_barc2[dir] = 0u;
            __threadfence();
            g_barg2[dir] = gen + 1u;
        } else {
            while (g_barg2[dir] == gen) { }
            __threadfence();
        }
    }
    __syncthreads();
}

// ================== split-tf32 tensor-core GEMM ===================================
// C[M,N] = A[M,K] @ W[N,K]^T (+bias / highway epilogue)
// block tile 128x128, k-stage 16, 8 warps (warp tile 64x32), double-buffered cp.async
#define BM 128
#define BN 128
#define BK 16
#define SS 20   // padded smem stride (conflict-free fragment loads: 20 ≡ conflict-free)

__device__ __forceinline__ void cp_async16(float* smem, const float* g) {
    uint32_t s = (uint32_t)__cvta_generic_to_shared(smem);
    asm volatile("cp.async.ca.shared.global [%0], [%1], 16;\n" :: "r"(s), "l"(g));
}
__device__ __forceinline__ void cp_commit() { asm volatile("cp.async.commit_group;\n"); }

__device__ __forceinline__ void tf32split(float x, uint32_t& hi, uint32_t& lo) {
    uint32_t h;
    asm("cvt.rna.tf32.f32 %0, %1;" : "=r"(h) : "f"(x));
    float l = x - __uint_as_float(h);
    asm("cvt.rna.tf32.f32 %0, %1;" : "=r"(lo) : "f"(l));
    hi = h;
}

__device__ __forceinline__ void mma_tf32(float* c, const uint32_t* a, const uint32_t* b) {
    asm volatile(
        "mma.sync.aligned.m16n8k8.row.col.f32.tf32.tf32.f32 "
        "{%0,%1,%2,%3}, {%4,%5,%6,%7}, {%8,%9}, {%0,%1,%2,%3};"
        : "+f"(c[0]), "+f"(c[1]), "+f"(c[2]), "+f"(c[3])
        : "r"(a[0]), "r"(a[1]), "r"(a[2]), "r"(a[3]), "r"(b[0]), "r"(b[1]));
}

// mode 0: C[row*N+col] = acc + bias[col]
// mode 1: g = sigmoid(acc + bias[col]); dst = g*A + (1-g)*prev   (N == K)
__global__ __launch_bounds__(256) void gemm_tf32(
    const float* __restrict__ A,
    const float* __restrict__ W,
    const float* __restrict__ bias,
    float* __restrict__ C,
    int N, int K, int mode,
    const float* __restrict__ prev,
    float* __restrict__ dst)
{
    __shared__ float As[2][BM * SS];
    __shared__ float Bs[2][BN * SS];

    const int tid  = threadIdx.x;
    const int bm   = blockIdx.y * BM;
    const int bn   = blockIdx.x * BN;
    const int warp = tid >> 5;
    const int lane = tid & 31;
    const int wm   = (warp & 1) * 64;
    const int wn   = (warp >> 1) * 32;
    const int gid  = lane >> 2;
    const int tig  = lane & 3;

    float acc[4][4][4];
#pragma unroll
    for (int mt = 0; mt < 4; mt++)
#pragma unroll
        for (int nt = 0; nt < 4; nt++)
#pragma unroll
            for (int r = 0; r < 4; r++) acc[mt][nt][r] = 0.f;

    const int r0l = tid >> 1;            // row handled for loads (two f4 per thread)
    const int q0  = (tid & 1) * 2;       // quad pair base

    // prologue: stage 0
    {
        const float* Ap = A + (size_t)(bm + r0l) * K;
        const float* Wp = W + (size_t)(bn + r0l) * K;
        cp_async16(&As[0][r0l * SS + q0 * 4],       Ap + q0 * 4);
        cp_async16(&As[0][r0l * SS + (q0 + 1) * 4], Ap + (q0 + 1) * 4);
        cp_async16(&Bs[0][r0l * SS + q0 * 4],       Wp + q0 * 4);
        cp_async16(&Bs[0][r0l * SS + (q0 + 1) * 4], Wp + (q0 + 1) * 4);
        cp_commit();
    }

    const int nk = K / BK;
    for (int ks = 0; ks < nk; ks++) {
        const int s = ks & 1;
        if (ks + 1 < nk) {
            const int k0 = (ks + 1) * BK;
            const float* Ap = A + (size_t)(bm + r0l) * K + k0;
            const float* Wp = W + (size_t)(bn + r0l) * K + k0;
            cp_async16(&As[s ^ 1][r0l * SS + q0 * 4],       Ap + q0 * 4);
            cp_async16(&As[s ^ 1][r0l * SS + (q0 + 1) * 4], Ap + (q0 + 1) * 4);
            cp_async16(&Bs[s ^ 1][r0l * SS + q0 * 4],       Wp + q0 * 4);
            cp_async16(&Bs[s ^ 1][r0l * SS + (q0 + 1) * 4], Wp + (q0 + 1) * 4);
            cp_commit();
            asm volatile("cp.async.wait_group 1;\n");
        } else {
            asm volatile("cp.async.wait_group 0;\n");
        }
        __syncthreads();

#pragma unroll
        for (int half = 0; half < 2; half++) {
            const int kk = half * 8;
            uint32_t ahi[4][4], alo[4][4];
#pragma unroll
            for (int mt = 0; mt < 4; mt++) {
                int row = wm + mt * 16 + gid;
                float a0 = As[s][row * SS + kk + tig];
                float a1 = As[s][(row + 8) * SS + kk + tig];
                float a2 = As[s][row * SS + kk + tig + 4];
                float a3 = As[s][(row + 8) * SS + kk + tig + 4];
                tf32split(a0, ahi[mt][0], alo[mt][0]);
                tf32split(a1, ahi[mt][1], alo[mt][1]);
                tf32split(a2, ahi[mt][2], alo[mt][2]);
                tf32split(a3, ahi[mt][3], alo[mt][3]);
            }
            uint32_t bhi[4][2], blo[4][2];
#pragma unroll
            for (int nt = 0; nt < 4; nt++) {
                int nrow = wn + nt * 8 + gid;
                float b0 = Bs[s][nrow * SS + kk + tig];
                float b1 = Bs[s][nrow * SS + kk + tig + 4];
                tf32split(b0, bhi[nt][0], blo[nt][0]);
                tf32split(b1, bhi[nt][1], blo[nt][1]);
            }
#pragma unroll
            for (int mt = 0; mt < 4; mt++)
#pragma unroll
                for (int nt = 0; nt < 4; nt++) {
                    mma_tf32(acc[mt][nt], ahi[mt], blo[nt]);
                    mma_tf32(acc[mt][nt], alo[mt], bhi[nt]);
                    mma_tf32(acc[mt][nt], ahi[mt], bhi[nt]);
                }
        }
        __syncthreads();
    }

    // epilogue
#pragma unroll
    for (int mt = 0; mt < 4; mt++) {
#pragma unroll
        for (int nt = 0; nt < 4; nt++) {
            int r0 = bm + wm + mt * 16 + gid;
            int c0 = bn + wn + nt * 8 + tig * 2;
            float bs0 = bias[c0], bs1 = bias[c0 + 1];
            if (mode == 0) {
                float2 v0 = { acc[mt][nt][0] + bs0, acc[mt][nt][1] + bs1 };
                float2 v1 = { acc[mt][nt][2] + bs0, acc[mt][nt][3] + bs1 };
                *(float2*)(C + (size_t)r0 * N + c0) = v0;
                *(float2*)(C + (size_t)(r0 + 8) * N + c0) = v1;
            } else {
#pragma unroll
                for (int rr = 0; rr < 2; rr++) {
                    int row = r0 + rr * 8;
                    size_t idx = (size_t)row * N + c0;
#pragma unroll
                    for (int cc = 0; cc < 2; cc++) {
                        float z = acc[mt][nt][rr * 2 + cc] + (cc ? bs1 : bs0);
                        float g = sigmoidf_(z);
                        float av = A[(size_t)row * K + c0 + cc];
                        dst[idx + cc] = g * av + (1.f - g) * prev[idx + cc];
                    }
                }
            }
        }
    }
}

// ---------------- persistent recurrent kernel -------------------------------------
// 128 blocks (64/dir), 128 threads. Block owns 8 hidden units (all 4 gates, all 64
// batches). Whh slice (32 rows x 512) staged once in shared, reused for 256 steps.
#define SM_WS (512 * 33)
#define SM_HS (64 * 65)
#define SMEM_REC ((SM_WS + SM_HS) * sizeof(float))

__global__ __launch_bounds__(128, 1) void lstm_rec(
    const float* __restrict__ Whh_f, const float* __restrict__ Whh_b,
    const float* __restrict__ init_f, const float* __restrict__ init_b,
    const float* __restrict__ masks,
    float* __restrict__ outbuf,   // [T,B,2H]; this dir writes cols [dir*H, dir*H+H)
    float* __restrict__ hn, float* __restrict__ cn,  // [6,B,H]
    int layer)
{
    extern __shared__ float sm[];
    float* Ws = sm;           // [512][33] transposed Whh slice (k-major, padded)
    float* hs = sm + SM_WS;   // [64][65]  h tile (batch-major, padded)

    const int dir = blockIdx.x >> 6;
    const int hb  = (blockIdx.x & 63) << 3;          // hidden base (8 units)
    const float* gbuf = dir ? g_gb : g_gf;
    const float* Whh  = dir ? Whh_b : Whh_f;
    const float* init = dir ? init_b : init_f;       // [2,512]: h0 then c0
    const int tid = threadIdx.x;
    const int hid = tid & 7;                         // local hidden unit
    const int b0  = (tid >> 3) << 2;                 // batch base (4 batches)
    const int hg  = hb + hid;                        // global hidden idx

    // stage weights: Ws[k][g*8+j] = Whh[g*512 + hb + j][k]
    for (int i = tid; i < 32 * 512; i += 128) {
        int c = i >> 9;            // 0..31
        int k = i & 511;
        int grow = ((c >> 3) << 9) + hb + (c & 7);
        Ws[k * 33 + c] = Whh[(size_t)grow * 512 + k];
    }

    float cst[4], hlast[4];
    {
        float c0 = init[512 + hg];
#pragma unroll
        for (int b = 0; b < 4; b++) { cst[b] = c0; hlast[b] = 0.f; }
    }
    __syncthreads();

    for (int t = 0; t < TSTEPS; ++t) {
        const int tg = dir ? (TSTEPS - 1 - t) : t;

        float ai[4], af[4], ag[4], ao[4];
        const float* gp = gbuf + (size_t)tg * NB * G4 + hg;
#pragma unroll
        for (int b = 0; b < 4; b++) {
            const float* r = gp + (size_t)(b0 + b) * G4;
            ai[b] = r[0]; af[b] = r[512]; ag[b] = r[1024]; ao[b] = r[1536];
        }

        const float* hsrc = &g_h[dir][(t + 1) & 1][0];  // (t-1)&1
        for (int k0 = 0; k0 < 512; k0 += 64) {
            __syncthreads();   // protect hs from previous tile's readers
            if (t == 0) {
                for (int i = tid; i < 64 * 64; i += 128) {
                    int bb = i >> 6, kk = i & 63;
                    hs[bb * 65 + kk] = init[k0 + kk];    // h0 broadcast over batch
                }
            } else {
                for (int i = tid; i < 64 * 64; i += 128) {
                    int bb = i >> 6, kk = i & 63;
                    hs[bb * 65 + kk] = hsrc[bb * 512 + k0 + kk];
                }
            }
            __syncthreads();
#pragma unroll 8
            for (int kk = 0; kk < 64; kk++) {
                const float* wrow = &Ws[(k0 + kk) * 33 + hid];
                float wi = wrow[0], wf = wrow[8], wg = wrow[16], wo = wrow[24];
#pragma unroll
                for (int b = 0; b < 4; b++) {
                    float hv = hs[(b0 + b) * 65 + kk];
                    ai[b] += hv * wi; af[b] += hv * wf;
                    ag[b] += hv * wg; ao[b] += hv * wo;
                }
            }
        }

        float* hdst = &g_h[dir][t & 1][0];
        float* od = outbuf + (size_t)tg * NB * D2H + dir * HID + hg;
#pragma unroll
        for (int b = 0; b < 4; b++) {
            float m = masks[tg * NB + b0 + b];
            float I = sigmoidf_(ai[b]);
            float F = sigmoidf_(af[b]);
            float Gv = tanhf(ag[b]);
            float O = sigmoidf_(ao[b]);
            float c = (F * cst[b] + I * Gv) * m;
            cst[b] = c;
            float h = O * tanhf(c) * m;
            hlast[b] = h;
            hdst[(b0 + b) * HID + hg] = h;
            od[(size_t)(b0 + b) * D2H] = h;
        }
        grid_barrier_dir(dir);
    }

    const int si = layer * 2 + dir;   // h_n order: fh0, bh0, fh1, bh1, fh2, bh2
#pragma unroll
    for (int b = 0; b < 4; b++) {
        hn[(size_t)si * NB * HID + (b0 + b) * HID + hg] = hlast[b];
        cn[(size_t)si * NB * HID + (b0 + b) * HID + hg] = cst[b];
    }
}

// ---------------- host ------------------------------------------------------------
extern "C" void kernel_launch(void* const* d_in, const int* in_sizes, int n_in,
                              void* d_out, int out_size)
{
    const float* x     = (const float*)d_in[0];   // [256,64,512]
    const float* masks = (const float*)d_in[1];   // [256,64,1]
    const float* fWih0 = (const float*)d_in[2];   // [2048,512]
    const float* fWihR = (const float*)d_in[3];   // [2,2048,1024]
    const float* fWhh  = (const float*)d_in[4];   // [3,2048,512]
    const float* fb    = (const float*)d_in[5];   // [3,2048]
    const float* bWih0 = (const float*)d_in[6];
    const float* bWihR = (const float*)d_in[7];
    const float* bWhh  = (const float*)d_in[8];
    const float* bb    = (const float*)d_in[9];
    const float* finit = (const float*)d_in[10];  // [3,2,512]
    const float* binit = (const float*)d_in[11];
    const float* projW = (const float*)d_in[12];  // [2,1024,1024]
    const float* projB = (const float*)d_in[13];  // [2,1024]

    float* out = (float*)d_out;                      // [256,64,1024]
    float* hn  = out + (size_t)MROWS * D2H;          // [6,64,512]
    float* cn  = hn + (size_t)6 * NB * HID;          // [6,64,512]

    float *gf, *gb, *feat0, *feat1, *lstmb;
    cudaGetSymbolAddress((void**)&gf, g_gf);
    cudaGetSymbolAddress((void**)&gb, g_gb);
    cudaGetSymbolAddress((void**)&feat0, g_feat0);
    cudaGetSymbolAddress((void**)&feat1, g_feat1);
    cudaGetSymbolAddress((void**)&lstmb, g_lstm);

    cudaFuncSetAttribute(lstm_rec, cudaFuncAttributeMaxDynamicSharedMemorySize,
                         (int)SMEM_REC);

    dim3 gg(G4 / BN, MROWS / BM);      // gates:  16 x 128
    dim3 gp(D2H / BN, MROWS / BM);     // proj:    8 x 128

    // ---- layer 0 (K = 512, input = x) ----
    gemm_tf32<<<gg, 256>>>(x, fWih0, fb, gf, G4, 512, 0, nullptr, nullptr);
    gemm_tf32<<<gg, 256>>>(x, bWih0, bb, gb, G4, 512, 0, nullptr, nullptr);
    lstm_rec<<<128, 128, SMEM_REC>>>(fWhh, bWhh, finit, binit, masks,
                                     feat0, hn, cn, 0);

    // ---- layer 1 (K = 1024, input = feat0) ----
    gemm_tf32<<<gg, 256>>>(feat0, fWihR, fb + 2048, gf, G4, 1024, 0, nullptr, nullptr);
    gemm_tf32<<<gg, 256>>>(feat0, bWihR, bb + 2048, gb, G4, 1024, 0, nullptr, nullptr);
    lstm_rec<<<128, 128, SMEM_REC>>>(fWhh + (size_t)2048 * 512,
                                     bWhh + (size_t)2048 * 512,
                                     finit + 1024, binit + 1024, masks,
                                     lstmb, hn, cn, 1);
    gemm_tf32<<<gp, 256>>>(lstmb, projW, projB, feat1, D2H, 1024, 1, feat0, feat1);

    // ---- layer 2 (K = 1024, input = feat1) ----
    gemm_tf32<<<gg, 256>>>(feat1, fWihR + (size_t)2048 * 1024, fb + 4096, gf,
                           G4, 1024, 0, nullptr, nullptr);
    gemm_tf32<<<gg, 256>>>(feat1, bWihR + (size_t)2048 * 1024, bb + 4096, gb,
                           G4, 1024, 0, nullptr, nullptr);
    lstm_rec<<<128, 128, SMEM_REC>>>(fWhh + (size_t)2 * 2048 * 512,
                                     bWhh + (size_t)2 * 2048 * 512,
                                     finit + 2048, binit + 2048, masks,
                                     lstmb, hn, cn, 2);
    gemm_tf32<<<gp, 256>>>(lstmb, projW + (size_t)1024 * 1024, projB + 1024,
                           out, D2H, 1024, 1, feat1, out);
}

// round 6
// speedup vs baseline: 1.2183x; 1.0233x over previous
#include <cuda_runtime.h>
#include <cuda_bf16.h>
#include <cstdint>
#include <cstddef>

#define TSTEPS 256
#define NB     64
#define HID    512
#define G4     2048
#define MROWS  (TSTEPS * NB)   // 16384
#define D2H    1024
#define K3MAX  3072

// ---------------- scratch (device globals; no allocation allowed) ----------------
__device__ float g_gf[(size_t)MROWS * G4];     // fwd gate pre-activations [T,B,4H]
__device__ float g_gb[(size_t)MROWS * G4];     // bwd gate pre-activations
__device__ float g_feat0[(size_t)MROWS * D2H]; // layer0 output
__device__ float g_feat1[(size_t)MROWS * D2H]; // layer1 highway output
__device__ float g_lstm[(size_t)MROWS * D2H];  // raw bilstm out for layers 1,2
__device__ float g_h[2][2][NB * HID];          // [dir][pingpong][B*H]
__device__ __nv_bfloat16 g_Abf[(size_t)MROWS * K3MAX];  // packed A' [hi|lo|hi]
__device__ __nv_bfloat16 g_Wbf[(size_t)G4 * K3MAX];     // packed W' [hi|hi|lo]
__device__ unsigned g_barc2[2];
__device__ volatile unsigned g_barg2[2];

__device__ __forceinline__ float sigmoidf_(float x) { return 1.f / (1.f + __expf(-x)); }

__device__ __forceinline__ void cp16(uint32_t s, const void* g) {
    asm volatile("cp.async.ca.shared.global [%0], [%1], 16;\n" :: "r"(s), "l"(g));
}
__device__ __forceinline__ void cp_commit() { asm volatile("cp.async.commit_group;\n"); }

__device__ __forceinline__ void ldm_x4(uint32_t& r0, uint32_t& r1, uint32_t& r2,
                                       uint32_t& r3, uint32_t addr) {
    asm volatile("ldmatrix.sync.aligned.m8n8.x4.shared.b16 {%0,%1,%2,%3}, [%4];"
                 : "=r"(r0), "=r"(r1), "=r"(r2), "=r"(r3) : "r"(addr));
}
__device__ __forceinline__ void mma_bf16(float* c, const uint32_t* a, const uint32_t* b) {
    asm volatile(
        "mma.sync.aligned.m16n8k16.row.col.f32.bf16.bf16.f32 "
        "{%0,%1,%2,%3}, {%4,%5,%6,%7}, {%8,%9}, {%0,%1,%2,%3};"
        : "+f"(c[0]), "+f"(c[1]), "+f"(c[2]), "+f"(c[3])
        : "r"(a[0]), "r"(a[1]), "r"(a[2]), "r"(a[3]), "r"(b[0]), "r"(b[1]));
}

// ---------------- bf16 hi/lo packing ----------------------------------------------
// mode 0 (activations): out = [hi | lo | hi] along K ; mode 1 (weights): [hi | hi | lo]
__global__ __launch_bounds__(256) void conv_pack(
    const float* __restrict__ src, __nv_bfloat16* __restrict__ dst,
    int K, int mode, int total)
{
    int i = (blockIdx.x * blockDim.x + threadIdx.x) * 2;
    if (i >= total) return;
    float2 v = *(const float2*)(src + i);
    __nv_bfloat16 h0 = __float2bfloat16(v.x);
    __nv_bfloat16 l0 = __float2bfloat16(v.x - __bfloat162float(h0));
    __nv_bfloat16 h1 = __float2bfloat16(v.y);
    __nv_bfloat16 l1 = __float2bfloat16(v.y - __bfloat162float(h1));
    __nv_bfloat162 h2 = { h0, h1 };
    __nv_bfloat162 l2 = { l0, l1 };
    int r = i / K, c = i - r * K;                 // K even, i even -> same row
    size_t base = (size_t)r * (3 * K) + c;
    *(__nv_bfloat162*)(dst + base) = h2;
    if (mode == 0) {
        *(__nv_bfloat162*)(dst + base + K)     = l2;
        *(__nv_bfloat162*)(dst + base + 2 * K) = h2;
    } else {
        *(__nv_bfloat162*)(dst + base + K)     = h2;
        *(__nv_bfloat162*)(dst + base + 2 * K) = l2;
    }
}

// ---------------- bf16 mma.sync GEMM: C[M,N] = A'[M,K3] @ W'[N,K3]^T --------------
// block 128x128, BK=32 bf16, 4-stage cp.async, 8 warps (warp tile 64x32), ldmatrix.
// mode 0: C = acc + bias ; mode 1: g = sigmoid(acc+bias); dst = g*Araw + (1-g)*prev
#define SSB   80                        // smem row stride bytes (40 bf16): conflict-free
#define STGB  (256 * SSB)               // A(128 rows)+B(128 rows) per stage = 20480 B
#define BOFF  (128 * SSB)               // B offset within stage
#define NSTG  4
#define GSMEM (NSTG * STGB)             // 81920 B

__global__ __launch_bounds__(256, 2) void bf_gemm(
    const __nv_bfloat16* __restrict__ A,
    const __nv_bfloat16* __restrict__ W,
    const float* __restrict__ bias,
    float* __restrict__ C,
    int Ncols, int K3, int mode,
    const float* __restrict__ Araw,
    const float* __restrict__ prev,
    float* __restrict__ dst)
{
    extern __shared__ char smem[];
    uint32_t sb;
    asm("{ .reg .u64 t; cvta.to.shared.u64 t, %1; cvt.u32.u64 %0, t; }"
        : "=r"(sb) : "l"(smem));

    const int tid  = threadIdx.x;
    const int warp = tid >> 5;
    const int lane = tid & 31;
    const int bm   = blockIdx.y * 128;
    const int bn   = blockIdx.x * 128;
    const int wm   = (warp & 1) * 64;
    const int wn   = (warp >> 1) * 32;
    const int gid  = lane >> 2;
    const int tig  = lane & 3;

    float acc[4][4][4];
#pragma unroll
    for (int mt = 0; mt < 4; mt++)
#pragma unroll
        for (int nt = 0; nt < 4; nt++)
#pragma unroll
            for (int r = 0; r < 4; r++) acc[mt][nt][r] = 0.f;

    const int nkc = K3 / 32;

    // each thread: 4 x 16B chunks per stage (1024 chunks: A 512 then B 512)
    auto issue_loads = [&](int kc) {
        const uint32_t st = sb + (kc & (NSTG - 1)) * STGB;
        const size_t kofs = (size_t)kc * 32;
#pragma unroll
        for (int j = 0; j < 4; j++) {
            int c   = tid + j * 256;
            int isB = c >> 9;
            int idx = c & 511;
            int row = idx >> 2;
            int q   = idx & 3;
            const __nv_bfloat16* gp = isB
                ? (W + (size_t)(bn + row) * K3 + kofs + q * 8)
                : (A + (size_t)(bm + row) * K3 + kofs + q * 8);
            cp16(st + isB * BOFF + row * SSB + q * 16, gp);
        }
        cp_commit();
    };

    issue_loads(0);
    if (nkc > 1) issue_loads(1);
    if (nkc > 2) issue_loads(2);

    for (int kc = 0; kc < nkc; kc++) {
        if (kc + 2 < nkc)      asm volatile("cp.async.wait_group 2;\n" ::: "memory");
        else if (kc + 1 < nkc) asm volatile("cp.async.wait_group 1;\n" ::: "memory");
        else                   asm volatile("cp.async.wait_group 0;\n" ::: "memory");
        __syncthreads();
        if (kc + 3 < nkc) issue_loads(kc + 3);

        const uint32_t st = sb + (kc & (NSTG - 1)) * STGB;
#pragma unroll
        for (int ks = 0; ks < 2; ks++) {
            const int k0b = ks * 32;                    // 16 bf16 = 32 bytes
            uint32_t a[4][4];
#pragma unroll
            for (int mt = 0; mt < 4; mt++) {
                uint32_t ad = st + (wm + mt * 16 + (lane & 15)) * SSB
                            + ((lane >> 4) * 16) + k0b;
                ldm_x4(a[mt][0], a[mt][1], a[mt][2], a[mt][3], ad);
            }
            uint32_t b[4][2];
#pragma unroll
            for (int np = 0; np < 2; np++) {
                uint32_t bd = st + BOFF
                            + (wn + np * 16 + (lane & 7) + ((lane >> 4) * 8)) * SSB
                            + (((lane >> 3) & 1) * 16) + k0b;
                ldm_x4(b[2 * np][0], b[2 * np][1], b[2 * np + 1][0], b[2 * np + 1][1], bd);
            }
#pragma unroll
            for (int mt = 0; mt < 4; mt++)
#pragma unroll
                for (int nt = 0; nt < 4; nt++)
                    mma_bf16(acc[mt][nt], a[mt], b[nt]);
        }
    }

    // epilogue
#pragma unroll
    for (int mt = 0; mt < 4; mt++) {
#pragma unroll
        for (int nt = 0; nt < 4; nt++) {
            int r0 = bm + wm + mt * 16 + gid;
            int c0 = bn + wn + nt * 8 + tig * 2;
            float bs0 = bias[c0], bs1 = bias[c0 + 1];
            if (mode == 0) {
                float2 v0 = { acc[mt][nt][0] + bs0, acc[mt][nt][1] + bs1 };
                float2 v1 = { acc[mt][nt][2] + bs0, acc[mt][nt][3] + bs1 };
                *(float2*)(C + (size_t)r0 * Ncols + c0) = v0;
                *(float2*)(C + (size_t)(r0 + 8) * Ncols + c0) = v1;
            } else {
#pragma unroll
                for (int rr = 0; rr < 2; rr++) {
                    int row = r0 + rr * 8;
                    size_t idx = (size_t)row * Ncols + c0;
                    float2 av = *(const float2*)(Araw + idx);
                    float2 pv = *(const float2*)(prev + idx);
                    float g0 = sigmoidf_(acc[mt][nt][rr * 2 + 0] + bs0);
                    float g1 = sigmoidf_(acc[mt][nt][rr * 2 + 1] + bs1);
                    float2 o = { g0 * av.x + (1.f - g0) * pv.x,
                                 g1 * av.y + (1.f - g1) * pv.y };
                    *(float2*)(dst + idx) = o;
                }
            }
        }
    }
}

// ---------------- grid barrier (per direction, 64 blocks) -------------------------
__device__ __forceinline__ void grid_barrier_dir(int dir) {
    __syncthreads();
    if (threadIdx.x == 0) {
        __threadfence();
        unsigned gen = g_barg2[dir];
        unsigned a = atomicAdd(&g_barc2[dir], 1u);
        if (a == 63u) {
            g_barc2[dir] = 0u;
            __threadfence();
            g_barg2[dir] = gen + 1u;
        } else {
            while (g_barg2[dir] == gen) { }
            __threadfence();
        }
    }
    __syncthreads();
}

// ---------------- persistent recurrent kernel (proven R2 version) -----------------
#define SM_WS (512 * 33)
#define SM_HS (64 * 65)
#define SMEM_REC ((SM_WS + SM_HS) * sizeof(float))

__global__ __launch_bounds__(128, 1) void lstm_rec(
    const float* __restrict__ Whh_f, const float* __restrict__ Whh_b,
    const float* __restrict__ init_f, const float* __restrict__ init_b,
    const float* __restrict__ masks,
    float* __restrict__ outbuf,   // [T,B,2H]; this dir writes cols [dir*H, dir*H+H)
    float* __restrict__ hn, float* __restrict__ cn,  // [6,B,H]
    int layer)
{
    extern __shared__ float sm[];
    float* Ws = sm;           // [512][33] transposed Whh slice (k-major, padded)
    float* hs = sm + SM_WS;   // [64][65]  h tile (batch-major, padded)

    const int dir = blockIdx.x >> 6;
    const int hb  = (blockIdx.x & 63) << 3;          // hidden base (8 units)
    const float* gbuf = dir ? g_gb : g_gf;
    const float* Whh  = dir ? Whh_b : Whh_f;
    const float* init = dir ? init_b : init_f;       // [2,512]: h0 then c0
    const int tid = threadIdx.x;
    const int hid = tid & 7;                         // local hidden unit
    const int b0  = (tid >> 3) << 2;                 // batch base (4 batches)
    const int hg  = hb + hid;                        // global hidden idx

    for (int i = tid; i < 32 * 512; i += 128) {
        int c = i >> 9;
        int k = i & 511;
        int grow = ((c >> 3) << 9) + hb + (c & 7);
        Ws[k * 33 + c] = Whh[(size_t)grow * 512 + k];
    }

    float cst[4], hlast[4];
    {
        float c0 = init[512 + hg];
#pragma unroll
        for (int b = 0; b < 4; b++) { cst[b] = c0; hlast[b] = 0.f; }
    }
    __syncthreads();

    for (int t = 0; t < TSTEPS; ++t) {
        const int tg = dir ? (TSTEPS - 1 - t) : t;

        float ai[4], af[4], ag[4], ao[4];
        const float* gp = gbuf + (size_t)tg * NB * G4 + hg;
#pragma unroll
        for (int b = 0; b < 4; b++) {
            const float* r = gp + (size_t)(b0 + b) * G4;
            ai[b] = r[0]; af[b] = r[512]; ag[b] = r[1024]; ao[b] = r[1536];
        }

        const float* hsrc = &g_h[dir][(t + 1) & 1][0];
        for (int k0 = 0; k0 < 512; k0 += 64) {
            __syncthreads();
            if (t == 0) {
                for (int i = tid; i < 64 * 64; i += 128) {
                    int bb = i >> 6, kk = i & 63;
                    hs[bb * 65 + kk] = init[k0 + kk];
                }
            } else {
                for (int i = tid; i < 64 * 64; i += 128) {
                    int bb = i >> 6, kk = i & 63;
                    hs[bb * 65 + kk] = hsrc[bb * 512 + k0 + kk];
                }
            }
            __syncthreads();
#pragma unroll 8
            for (int kk = 0; kk < 64; kk++) {
                const float* wrow = &Ws[(k0 + kk) * 33 + hid];
                float wi = wrow[0], wf = wrow[8], wg = wrow[16], wo = wrow[24];
#pragma unroll
                for (int b = 0; b < 4; b++) {
                    float hv = hs[(b0 + b) * 65 + kk];
                    ai[b] += hv * wi; af[b] += hv * wf;
                    ag[b] += hv * wg; ao[b] += hv * wo;
                }
            }
        }

        float* hdst = &g_h[dir][t & 1][0];
        float* od = outbuf + (size_t)tg * NB * D2H + dir * HID + hg;
#pragma unroll
        for (int b = 0; b < 4; b++) {
            float m = masks[tg * NB + b0 + b];
            float I = sigmoidf_(ai[b]);
            float F = sigmoidf_(af[b]);
            float Gv = tanhf(ag[b]);
            float O = sigmoidf_(ao[b]);
            float c = (F * cst[b] + I * Gv) * m;
            cst[b] = c;
            float h = O * tanhf(c) * m;
            hlast[b] = h;
            hdst[(b0 + b) * HID + hg] = h;
            od[(size_t)(b0 + b) * D2H] = h;
        }
        grid_barrier_dir(dir);
    }

    const int si = layer * 2 + dir;
#pragma unroll
    for (int b = 0; b < 4; b++) {
        hn[(size_t)si * NB * HID + (b0 + b) * HID + hg] = hlast[b];
        cn[(size_t)si * NB * HID + (b0 + b) * HID + hg] = cst[b];
    }
}

// ---------------- host ------------------------------------------------------------
extern "C" void kernel_launch(void* const* d_in, const int* in_sizes, int n_in,
                              void* d_out, int out_size)
{
    const float* x     = (const float*)d_in[0];   // [256,64,512]
    const float* masks = (const float*)d_in[1];   // [256,64,1]
    const float* fWih0 = (const float*)d_in[2];   // [2048,512]
    const float* fWihR = (const float*)d_in[3];   // [2,2048,1024]
    const float* fWhh  = (const float*)d_in[4];   // [3,2048,512]
    const float* fb    = (const float*)d_in[5];   // [3,2048]
    const float* bWih0 = (const float*)d_in[6];
    const float* bWihR = (const float*)d_in[7];
    const float* bWhh  = (const float*)d_in[8];
    const float* bb    = (const float*)d_in[9];
    const float* finit = (const float*)d_in[10];  // [3,2,512]
    const float* binit = (const float*)d_in[11];
    const float* projW = (const float*)d_in[12];  // [2,1024,1024]
    const float* projB = (const float*)d_in[13];  // [2,1024]

    float* out = (float*)d_out;                      // [256,64,1024]
    float* hn  = out + (size_t)MROWS * D2H;          // [6,64,512]
    float* cn  = hn + (size_t)6 * NB * HID;          // [6,64,512]

    float *gf, *gb, *feat0, *feat1, *lstmb;
    __nv_bfloat16 *Abf, *Wbf;
    cudaGetSymbolAddress((void**)&gf, g_gf);
    cudaGetSymbolAddress((void**)&gb, g_gb);
    cudaGetSymbolAddress((void**)&feat0, g_feat0);
    cudaGetSymbolAddress((void**)&feat1, g_feat1);
    cudaGetSymbolAddress((void**)&lstmb, g_lstm);
    cudaGetSymbolAddress((void**)&Abf, g_Abf);
    cudaGetSymbolAddress((void**)&Wbf, g_Wbf);

    cudaFuncSetAttribute(lstm_rec, cudaFuncAttributeMaxDynamicSharedMemorySize,
                         (int)SMEM_REC);
    cudaFuncSetAttribute(bf_gemm, cudaFuncAttributeMaxDynamicSharedMemorySize,
                         (int)GSMEM);

    dim3 gg(G4 / 128, MROWS / 128);    // gates:  16 x 128
    dim3 gp(D2H / 128, MROWS / 128);   // proj:    8 x 128
    const int CT = 256;

    auto packA = [&](const float* src, int K) {
        int tot = MROWS * K;
        conv_pack<<<(tot / 2 + CT - 1) / CT, CT>>>(src, Abf, K, 0, tot);
    };
    auto packW = [&](const float* src, int N, int K) {
        int tot = N * K;
        conv_pack<<<(tot / 2 + CT - 1) / CT, CT>>>(src, Wbf, K, 1, tot);
    };

    // ---- layer 0 (K=512 -> K3=1536) ----
    packA(x, 512);
    packW(fWih0, G4, 512);
    bf_gemm<<<gg, 256, GSMEM>>>(Abf, Wbf, fb, gf, G4, 1536, 0, nullptr, nullptr, nullptr);
    packW(bWih0, G4, 512);
    bf_gemm<<<gg, 256, GSMEM>>>(Abf, Wbf, bb, gb, G4, 1536, 0, nullptr, nullptr, nullptr);
    lstm_rec<<<128, 128, SMEM_REC>>>(fWhh, bWhh, finit, binit, masks,
                                     feat0, hn, cn, 0);

    // ---- layer 1 (K=1024 -> K3=3072) ----
    packA(feat0, 1024);
    packW(fWihR, G4, 1024);
    bf_gemm<<<gg, 256, GSMEM>>>(Abf, Wbf, fb + 2048, gf, G4, 3072, 0, nullptr, nullptr, nullptr);
    packW(bWihR, G4, 1024);
    bf_gemm<<<gg, 256, GSMEM>>>(Abf, Wbf, bb + 2048, gb, G4, 3072, 0, nullptr, nullptr, nullptr);
    lstm_rec<<<128, 128, SMEM_REC>>>(fWhh + (size_t)2048 * 512,
                                     bWhh + (size_t)2048 * 512,
                                     finit + 1024, binit + 1024, masks,
                                     lstmb, hn, cn, 1);
    packA(lstmb, 1024);
    packW(projW, D2H, 1024);
    bf_gemm<<<gp, 256, GSMEM>>>(Abf, Wbf, projB, feat1, D2H, 3072, 1,
                                lstmb, feat0, feat1);

    // ---- layer 2 (K=1024 -> K3=3072) ----
    packA(feat1, 1024);
    packW(fWihR + (size_t)2048 * 1024, G4, 1024);
    bf_gemm<<<gg, 256, GSMEM>>>(Abf, Wbf, fb + 4096, gf, G4, 3072, 0, nullptr, nullptr, nullptr);
    packW(bWihR + (size_t)2048 * 1024, G4, 1024);
    bf_gemm<<<gg, 256, GSMEM>>>(Abf, Wbf, bb + 4096, gb, G4, 3072, 0, nullptr, nullptr, nullptr);
    lstm_rec<<<128, 128, SMEM_REC>>>(fWhh + (size_t)2 * 2048 * 512,
                                     bWhh + (size_t)2 * 2048 * 512,
                                     finit + 2048, binit + 2048, masks,
                                     lstmb, hn, cn, 2);
    packA(lstmb, 1024);
    packW(projW + (size_t)1024 * 1024, D2H, 1024);
    bf_gemm<<<gp, 256, GSMEM>>>(Abf, Wbf, projB + 1024, out, D2H, 3072, 1,
                                lstmb, feat1, out);
}

// round 8
// speedup vs baseline: 2.0104x; 1.6501x over previous
#include <cuda_runtime.h>
#include <cuda_bf16.h>
#include <cstdint>
#include <cstddef>

#define TSTEPS 256
#define NB     64
#define HID    512
#define G4     2048
#define MROWS  (TSTEPS * NB)   // 16384
#define D2H    1024
#define K3MAX  3072

// ---------------- scratch (device globals; no allocation allowed) ----------------
__device__ float g_gf[(size_t)MROWS * G4];     // fwd gate pre-activations [T,B,4H]
__device__ float g_gb[(size_t)MROWS * G4];     // bwd gate pre-activations
__device__ float g_feat0[(size_t)MROWS * D2H]; // layer0 output
__device__ float g_feat1[(size_t)MROWS * D2H]; // layer1 highway output
__device__ float g_lstm[(size_t)MROWS * D2H];  // raw bilstm out for layers 1,2
__device__ float g_h[2][2][NB * HID];          // [dir][pingpong][B*H]
__device__ __nv_bfloat16 g_Abf[(size_t)MROWS * K3MAX];  // packed A' [hi|lo|hi]
__device__ __nv_bfloat16 g_Wbf[(size_t)G4 * K3MAX];     // packed W' [hi|hi|lo]
__device__ unsigned g_barc2[2];
__device__ volatile unsigned g_barg2[2];

__device__ __forceinline__ float sigmoidf_(float x) { return 1.f / (1.f + __expf(-x)); }

__device__ __forceinline__ void cp16(uint32_t s, const void* g) {
    asm volatile("cp.async.ca.shared.global [%0], [%1], 16;\n" :: "r"(s), "l"(g));
}
__device__ __forceinline__ void cp_commit() { asm volatile("cp.async.commit_group;\n"); }

__device__ __forceinline__ void ldm_x4(uint32_t& r0, uint32_t& r1, uint32_t& r2,
                                       uint32_t& r3, uint32_t addr) {
    asm volatile("ldmatrix.sync.aligned.m8n8.x4.shared.b16 {%0,%1,%2,%3}, [%4];"
                 : "=r"(r0), "=r"(r1), "=r"(r2), "=r"(r3) : "r"(addr));
}
__device__ __forceinline__ void mma_bf16(float* c, const uint32_t* a, const uint32_t* b) {
    asm volatile(
        "mma.sync.aligned.m16n8k16.row.col.f32.bf16.bf16.f32 "
        "{%0,%1,%2,%3}, {%4,%5,%6,%7}, {%8,%9}, {%0,%1,%2,%3};"
        : "+f"(c[0]), "+f"(c[1]), "+f"(c[2]), "+f"(c[3])
        : "r"(a[0]), "r"(a[1]), "r"(a[2]), "r"(a[3]), "r"(b[0]), "r"(b[1]));
}

// ---------------- bf16 hi/lo packing ----------------------------------------------
// mode 0 (activations): out = [hi | lo | hi] along K ; mode 1 (weights): [hi | hi | lo]
__global__ __launch_bounds__(256) void conv_pack(
    const float* __restrict__ src, __nv_bfloat16* __restrict__ dst,
    int K, int mode, int total)
{
    int i = (blockIdx.x * blockDim.x + threadIdx.x) * 2;
    if (i >= total) return;
    float2 v = *(const float2*)(src + i);
    __nv_bfloat16 h0 = __float2bfloat16(v.x);
    __nv_bfloat16 l0 = __float2bfloat16(v.x - __bfloat162float(h0));
    __nv_bfloat16 h1 = __float2bfloat16(v.y);
    __nv_bfloat16 l1 = __float2bfloat16(v.y - __bfloat162float(h1));
    __nv_bfloat162 h2 = { h0, h1 };
    __nv_bfloat162 l2 = { l0, l1 };
    int r = i / K, c = i - r * K;                 // K even, i even -> same row
    size_t base = (size_t)r * (3 * K) + c;
    *(__nv_bfloat162*)(dst + base) = h2;
    if (mode == 0) {
        *(__nv_bfloat162*)(dst + base + K)     = l2;
        *(__nv_bfloat162*)(dst + base + 2 * K) = h2;
    } else {
        *(__nv_bfloat162*)(dst + base + K)     = h2;
        *(__nv_bfloat162*)(dst + base + 2 * K) = l2;
    }
}

// ---------------- bf16 mma.sync GEMM (unchanged, proven in R6) --------------------
#define SSB   80
#define STGB  (256 * SSB)
#define BOFF  (128 * SSB)
#define NSTG  4
#define GSMEM (NSTG * STGB)

__global__ __launch_bounds__(256, 2) void bf_gemm(
    const __nv_bfloat16* __restrict__ A,
    const __nv_bfloat16* __restrict__ W,
    const float* __restrict__ bias,
    float* __restrict__ C,
    int Ncols, int K3, int mode,
    const float* __restrict__ Araw,
    const float* __restrict__ prev,
    float* __restrict__ dst)
{
    extern __shared__ char smem[];
    uint32_t sb;
    asm("{ .reg .u64 t; cvta.to.shared.u64 t, %1; cvt.u32.u64 %0, t; }"
        : "=r"(sb) : "l"(smem));

    const int tid  = threadIdx.x;
    const int warp = tid >> 5;
    const int lane = tid & 31;
    const int bm   = blockIdx.y * 128;
    const int bn   = blockIdx.x * 128;
    const int wm   = (warp & 1) * 64;
    const int wn   = (warp >> 1) * 32;
    const int gid  = lane >> 2;
    const int tig  = lane & 3;

    float acc[4][4][4];
#pragma unroll
    for (int mt = 0; mt < 4; mt++)
#pragma unroll
        for (int nt = 0; nt < 4; nt++)
#pragma unroll
            for (int r = 0; r < 4; r++) acc[mt][nt][r] = 0.f;

    const int nkc = K3 / 32;

    auto issue_loads = [&](int kc) {
        const uint32_t st = sb + (kc & (NSTG - 1)) * STGB;
        const size_t kofs = (size_t)kc * 32;
#pragma unroll
        for (int j = 0; j < 4; j++) {
            int c   = tid + j * 256;
            int isB = c >> 9;
            int idx = c & 511;
            int row = idx >> 2;
            int q   = idx & 3;
            const __nv_bfloat16* gp = isB
                ? (W + (size_t)(bn + row) * K3 + kofs + q * 8)
                : (A + (size_t)(bm + row) * K3 + kofs + q * 8);
            cp16(st + isB * BOFF + row * SSB + q * 16, gp);
        }
        cp_commit();
    };

    issue_loads(0);
    if (nkc > 1) issue_loads(1);
    if (nkc > 2) issue_loads(2);

    for (int kc = 0; kc < nkc; kc++) {
        if (kc + 2 < nkc)      asm volatile("cp.async.wait_group 2;\n" ::: "memory");
        else if (kc + 1 < nkc) asm volatile("cp.async.wait_group 1;\n" ::: "memory");
        else                   asm volatile("cp.async.wait_group 0;\n" ::: "memory");
        __syncthreads();
        if (kc + 3 < nkc) issue_loads(kc + 3);

        const uint32_t st = sb + (kc & (NSTG - 1)) * STGB;
#pragma unroll
        for (int ks = 0; ks < 2; ks++) {
            const int k0b = ks * 32;
            uint32_t a[4][4];
#pragma unroll
            for (int mt = 0; mt < 4; mt++) {
                uint32_t ad = st + (wm + mt * 16 + (lane & 15)) * SSB
                            + ((lane >> 4) * 16) + k0b;
                ldm_x4(a[mt][0], a[mt][1], a[mt][2], a[mt][3], ad);
            }
            uint32_t b[4][2];
#pragma unroll
            for (int np = 0; np < 2; np++) {
                uint32_t bd = st + BOFF
                            + (wn + np * 16 + (lane & 7) + ((lane >> 4) * 8)) * SSB
                            + (((lane >> 3) & 1) * 16) + k0b;
                ldm_x4(b[2 * np][0], b[2 * np][1], b[2 * np + 1][0], b[2 * np + 1][1], bd);
            }
#pragma unroll
            for (int mt = 0; mt < 4; mt++)
#pragma unroll
                for (int nt = 0; nt < 4; nt++)
                    mma_bf16(acc[mt][nt], a[mt], b[nt]);
        }
    }

#pragma unroll
    for (int mt = 0; mt < 4; mt++) {
#pragma unroll
        for (int nt = 0; nt < 4; nt++) {
            int r0 = bm + wm + mt * 16 + gid;
            int c0 = bn + wn + nt * 8 + tig * 2;
            float bs0 = bias[c0], bs1 = bias[c0 + 1];
            if (mode == 0) {
                float2 v0 = { acc[mt][nt][0] + bs0, acc[mt][nt][1] + bs1 };
                float2 v1 = { acc[mt][nt][2] + bs0, acc[mt][nt][3] + bs1 };
                *(float2*)(C + (size_t)r0 * Ncols + c0) = v0;
                *(float2*)(C + (size_t)(r0 + 8) * Ncols + c0) = v1;
            } else {
#pragma unroll
                for (int rr = 0; rr < 2; rr++) {
                    int row = r0 + rr * 8;
                    size_t idx = (size_t)row * Ncols + c0;
                    float2 av = *(const float2*)(Araw + idx);
                    float2 pv = *(const float2*)(prev + idx);
                    float g0 = sigmoidf_(acc[mt][nt][rr * 2 + 0] + bs0);
                    float g1 = sigmoidf_(acc[mt][nt][rr * 2 + 1] + bs1);
                    float2 o = { g0 * av.x + (1.f - g0) * pv.x,
                                 g1 * av.y + (1.f - g1) * pv.y };
                    *(float2*)(dst + idx) = o;
                }
            }
        }
    }
}

// ---------------- grid barrier (per direction, 64 blocks) -------------------------
__device__ __forceinline__ void grid_barrier_dir(int dir) {
    __syncthreads();
    if (threadIdx.x == 0) {
        __threadfence();
        unsigned gen = g_barg2[dir];
        unsigned a = atomicAdd(&g_barc2[dir], 1u);
        if (a == 63u) {
            g_barc2[dir] = 0u;
            __threadfence();
            g_barg2[dir] = gen + 1u;
        } else {
            while (g_barg2[dir] == gen) { }
            __threadfence();
        }
    }
    __syncthreads();
}

// ---------------- persistent recurrent kernel v2 ----------------------------------
// 128 blocks (64/dir), 256 threads (8 warps). Block owns 8 hidden units.
// Thread: (hid = tid&7, 2 batches). Weights as float4 {wi,wf,wg,wo} per (k,hid).
// h tiles k-major (stride 65), double-buffered with LDG prefetch.
// Gate pre-activations + masks for step t+1 prefetched into regs before barrier.
#define SM_W4F   16384                // Wq floats (4096 float4)
#define SM_TILE  (64 * 65)            // floats per h tile buffer
#define SMEM_REC ((SM_W4F + 2 * SM_TILE) * sizeof(float))   // 98816 B

__global__ __launch_bounds__(256, 1) void lstm_rec(
    const float* __restrict__ Whh_f, const float* __restrict__ Whh_b,
    const float* __restrict__ init_f, const float* __restrict__ init_b,
    const float* __restrict__ masks,
    float* __restrict__ outbuf,   // [T,B,2H]; this dir writes cols [dir*H, dir*H+H)
    float* __restrict__ hn, float* __restrict__ cn,  // [6,B,H]
    int layer)
{
    extern __shared__ float sm[];
    float4* Wq  = (float4*)sm;            // [512*8] : (k, hid) -> {wi,wf,wg,wo}
    float*  hs0 = sm + SM_W4F;
    float*  hs1 = hs0 + SM_TILE;

    const int dir = blockIdx.x >> 6;
    const int hb  = (blockIdx.x & 63) << 3;
    const float* gbuf = dir ? g_gb : g_gf;
    const float* Whh  = dir ? Whh_b : Whh_f;
    const float* init = dir ? init_b : init_f;       // [2,512]: h0 then c0
    const int tid = threadIdx.x;
    const int hid = tid & 7;
    const int b0  = (tid >> 3) * 2;                  // 2 batches per thread
    const int hg  = hb + hid;

    // stage weights: Wq[k*8+hid] = {Whh[hg][k], Whh[512+hg][k], Whh[1024+hg][k], Whh[1536+hg][k]}
    for (int i = tid; i < 4096; i += 256) {
        int k = i >> 3, hl = i & 7, row = hb + hl;
        Wq[i] = make_float4(Whh[(size_t)row * 512 + k],
                            Whh[(size_t)(512 + row) * 512 + k],
                            Whh[(size_t)(1024 + row) * 512 + k],
                            Whh[(size_t)(1536 + row) * 512 + k]);
    }

    float cst[2], hlast[2];
    cst[0] = cst[1] = init[512 + hg];
    hlast[0] = hlast[1] = 0.f;

    // prefetch step-0 gates + masks
    float pg[8], pm[2];
    {
        const int tg = dir ? (TSTEPS - 1) : 0;
        const float* gp = gbuf + (size_t)tg * NB * G4 + hg;
#pragma unroll
        for (int b = 0; b < 2; b++) {
            const float* r = gp + (size_t)(b0 + b) * G4;
            pg[b * 4 + 0] = r[0];    pg[b * 4 + 1] = r[512];
            pg[b * 4 + 2] = r[1024]; pg[b * 4 + 3] = r[1536];
            pm[b] = masks[tg * NB + b0 + b];
        }
    }
    __syncthreads();   // weights visible

    for (int t = 0; t < TSTEPS; ++t) {
        const int tg = dir ? (TSTEPS - 1 - t) : t;
        float ai[2] = { pg[0], pg[4] }, af[2] = { pg[1], pg[5] };
        float ag[2] = { pg[2], pg[6] }, ao[2] = { pg[3], pg[7] };
        const float* hsrc = &g_h[dir][(t + 1) & 1][0];

        float4 ld[4];
        // load tile j into regs (global, coalesced 256B runs; t==0 -> broadcast h0)
        auto ldt = [&](int j) {
            const int k0 = j * 64;
#pragma unroll
            for (int r = 0; r < 4; r++) {
                int flat = tid + r * 256;       // [0,1024)
                int bb = flat >> 4, kq = flat & 15;
                if (t == 0) {
                    ld[r].x = init[k0 + kq * 4 + 0];
                    ld[r].y = init[k0 + kq * 4 + 1];
                    ld[r].z = init[k0 + kq * 4 + 2];
                    ld[r].w = init[k0 + kq * 4 + 3];
                    (void)bb;
                } else {
                    ld[r] = *(const float4*)(hsrc + bb * 512 + k0 + kq * 4);
                }
            }
        };
        // store regs -> tile buffer (k-major, stride 65)
        auto stt = [&](float* buf) {
#pragma unroll
            for (int r = 0; r < 4; r++) {
                int flat = tid + r * 256;
                int bb = flat >> 4, kq = flat & 15;
                buf[(kq * 4 + 0) * 65 + bb] = ld[r].x;
                buf[(kq * 4 + 1) * 65 + bb] = ld[r].y;
                buf[(kq * 4 + 2) * 65 + bb] = ld[r].z;
                buf[(kq * 4 + 3) * 65 + bb] = ld[r].w;
            }
        };

        ldt(0); stt(hs0); __syncthreads();
        float* bufs[2] = { hs0, hs1 };
#pragma unroll 1
        for (int j = 0; j < 8; j++) {
            if (j < 7) ldt(j + 1);                  // prefetch next tile (LDG in flight)
            const float* cb = bufs[j & 1];
            const float4* wp = Wq + (j * 64) * 8 + hid;
#pragma unroll 16
            for (int kk = 0; kk < 64; kk++) {
                float4 w = wp[kk * 8];
                float h0 = cb[kk * 65 + b0];
                float h1 = cb[kk * 65 + b0 + 1];
                ai[0] += h0 * w.x; af[0] += h0 * w.y; ag[0] += h0 * w.z; ao[0] += h0 * w.w;
                ai[1] += h1 * w.x; af[1] += h1 * w.y; ag[1] += h1 * w.z; ao[1] += h1 * w.w;
            }
            if (j < 7) { stt(bufs[(j + 1) & 1]); __syncthreads(); }
        }

        float* hdst = &g_h[dir][t & 1][0];
        float* od = outbuf + (size_t)tg * NB * D2H + dir * HID + hg;
#pragma unroll
        for (int b = 0; b < 2; b++) {
            float m = pm[b];
            float I  = sigmoidf_(ai[b]);
            float F  = sigmoidf_(af[b]);
            float Gv = tanhf(ag[b]);
            float O  = sigmoidf_(ao[b]);
            float c = (F * cst[b] + I * Gv) * m;
            cst[b] = c;
            float h = O * tanhf(c) * m;
            hlast[b] = h;
            hdst[(b0 + b) * HID + hg] = h;
            od[(size_t)(b0 + b) * D2H] = h;
        }

        // prefetch next step's gates + masks (hidden behind barrier + tile0)
        if (t + 1 < TSTEPS) {
            const int tn = dir ? (TSTEPS - 2 - t) : (t + 1);
            const float* gp = gbuf + (size_t)tn * NB * G4 + hg;
#pragma unroll
            for (int b = 0; b < 2; b++) {
                const float* r = gp + (size_t)(b0 + b) * G4;
                pg[b * 4 + 0] = r[0];    pg[b * 4 + 1] = r[512];
                pg[b * 4 + 2] = r[1024]; pg[b * 4 + 3] = r[1536];
                pm[b] = masks[tn * NB + b0 + b];
            }
        }
        grid_barrier_dir(dir);
    }

    const int si = layer * 2 + dir;   // h_n order: fh0, bh0, fh1, bh1, fh2, bh2
#pragma unroll
    for (int b = 0; b < 2; b++) {
        hn[(size_t)si * NB * HID + (b0 + b) * HID + hg] = hlast[b];
        cn[(size_t)si * NB * HID + (b0 + b) * HID + hg] = cst[b];
    }
}

// ---------------- host ------------------------------------------------------------
extern "C" void kernel_launch(void* const* d_in, const int* in_sizes, int n_in,
                              void* d_out, int out_size)
{
    const float* x     = (const float*)d_in[0];   // [256,64,512]
    const float* masks = (const float*)d_in[1];   // [256,64,1]
    const float* fWih0 = (const float*)d_in[2];   // [2048,512]
    const float* fWihR = (const float*)d_in[3];   // [2,2048,1024]
    const float* fWhh  = (const float*)d_in[4];   // [3,2048,512]
    const float* fb    = (const float*)d_in[5];   // [3,2048]
    const float* bWih0 = (const float*)d_in[6];
    const float* bWihR = (const float*)d_in[7];
    const float* bWhh  = (const float*)d_in[8];
    const float* bb    = (const float*)d_in[9];
    const float* finit = (const float*)d_in[10];  // [3,2,512]
    const float* binit = (const float*)d_in[11];
    const float* projW = (const float*)d_in[12];  // [2,1024,1024]
    const float* projB = (const float*)d_in[13];  // [2,1024]

    float* out = (float*)d_out;                      // [256,64,1024]
    float* hn  = out + (size_t)MROWS * D2H;          // [6,64,512]
    float* cn  = hn + (size_t)6 * NB * HID;          // [6,64,512]

    float *gf, *gb, *feat0, *feat1, *lstmb;
    __nv_bfloat16 *Abf, *Wbf;
    cudaGetSymbolAddress((void**)&gf, g_gf);
    cudaGetSymbolAddress((void**)&gb, g_gb);
    cudaGetSymbolAddress((void**)&feat0, g_feat0);
    cudaGetSymbolAddress((void**)&feat1, g_feat1);
    cudaGetSymbolAddress((void**)&lstmb, g_lstm);
    cudaGetSymbolAddress((void**)&Abf, g_Abf);
    cudaGetSymbolAddress((void**)&Wbf, g_Wbf);

    cudaFuncSetAttribute(lstm_rec, cudaFuncAttributeMaxDynamicSharedMemorySize,
                         (int)SMEM_REC);
    cudaFuncSetAttribute(bf_gemm, cudaFuncAttributeMaxDynamicSharedMemorySize,
                         (int)GSMEM);

    dim3 gg(G4 / 128, MROWS / 128);    // gates:  16 x 128
    dim3 gp(D2H / 128, MROWS / 128);   // proj:    8 x 128
    const int CT = 256;

    auto packA = [&](const float* src, int K) {
        int tot = MROWS * K;
        conv_pack<<<(tot / 2 + CT - 1) / CT, CT>>>(src, Abf, K, 0, tot);
    };
    auto packW = [&](const float* src, int N, int K) {
        int tot = N * K;
        conv_pack<<<(tot / 2 + CT - 1) / CT, CT>>>(src, Wbf, K, 1, tot);
    };

    // ---- layer 0 (K=512 -> K3=1536) ----
    packA(x, 512);
    packW(fWih0, G4, 512);
    bf_gemm<<<gg, 256, GSMEM>>>(Abf, Wbf, fb, gf, G4, 1536, 0, nullptr, nullptr, nullptr);
    packW(bWih0, G4, 512);
    bf_gemm<<<gg, 256, GSMEM>>>(Abf, Wbf, bb, gb, G4, 1536, 0, nullptr, nullptr, nullptr);
    lstm_rec<<<128, 256, SMEM_REC>>>(fWhh, bWhh, finit, binit, masks,
                                     feat0, hn, cn, 0);

    // ---- layer 1 (K=1024 -> K3=3072) ----
    packA(feat0, 1024);
    packW(fWihR, G4, 1024);
    bf_gemm<<<gg, 256, GSMEM>>>(Abf, Wbf, fb + 2048, gf, G4, 3072, 0, nullptr, nullptr, nullptr);
    packW(bWihR, G4, 1024);
    bf_gemm<<<gg, 256, GSMEM>>>(Abf, Wbf, bb + 2048, gb, G4, 3072, 0, nullptr, nullptr, nullptr);
    lstm_rec<<<128, 256, SMEM_REC>>>(fWhh + (size_t)2048 * 512,
                                     bWhh + (size_t)2048 * 512,
                                     finit + 1024, binit + 1024, masks,
                                     lstmb, hn, cn, 1);
    packA(lstmb, 1024);
    packW(projW, D2H, 1024);
    bf_gemm<<<gp, 256, GSMEM>>>(Abf, Wbf, projB, feat1, D2H, 3072, 1,
                                lstmb, feat0, feat1);

    // ---- layer 2 (K=1024 -> K3=3072) ----
    packA(feat1, 1024);
    packW(fWihR + (size_t)2048 * 1024, G4, 1024);
    bf_gemm<<<gg, 256, GSMEM>>>(Abf, Wbf, fb + 4096, gf, G4, 3072, 0, nullptr, nullptr, nullptr);
    packW(bWihR + (size_t)2048 * 1024, G4, 1024);
    bf_gemm<<<gg, 256, GSMEM>>>(Abf, Wbf, bb + 4096, gb, G4, 3072, 0, nullptr, nullptr, nullptr);
    lstm_rec<<<128, 256, SMEM_REC>>>(fWhh + (size_t)2 * 2048 * 512,
                                     bWhh + (size_t)2 * 2048 * 512,
                                     finit + 2048, binit + 2048, masks,
                                     lstmb, hn, cn, 2);
    packA(lstmb, 1024);
    packW(projW + (size_t)1024 * 1024, D2H, 1024);
    bf_gemm<<<gp, 256, GSMEM>>>(Abf, Wbf, projB + 1024, out, D2H, 3072, 1,
                                lstmb, feat1, out);
}

// round 9
// speedup vs baseline: 2.1284x; 1.0587x over previous
#include <cuda_runtime.h>
#include <cuda_fp16.h>
#include <cstdint>
#include <cstddef>

#define TSTEPS 256
#define NB     64
#define HID    512
#define G4     2048
#define MROWS  (TSTEPS * NB)   // 16384
#define D2H    1024

// ---------------- scratch (device globals; no allocation allowed) ----------------
__device__ float g_gf[(size_t)MROWS * G4];     // fwd gate pre-activations [T,B,4H]
__device__ float g_gb[(size_t)MROWS * G4];     // bwd gate pre-activations
__device__ float g_feat0[(size_t)MROWS * D2H]; // layer0 output
__device__ float g_feat1[(size_t)MROWS * D2H]; // layer1 highway output
__device__ float g_lstm[(size_t)MROWS * D2H];  // raw bilstm out for layers 1,2
__device__ float g_h[2][2][NB * HID];          // [dir][pingpong][B*H]
__device__ __half g_Ahf[(size_t)MROWS * 2048]; // packed A' [hi | lo], row stride 2K
__device__ __half g_Whf[(size_t)G4 * 1024];    // packed W  (single fp16), row stride K
__device__ unsigned g_barc2[2];
__device__ volatile unsigned g_barg2[2];

__device__ __forceinline__ float sigmoidf_(float x) { return 1.f / (1.f + __expf(-x)); }

__device__ __forceinline__ void cp16(uint32_t s, const void* g) {
    asm volatile("cp.async.ca.shared.global [%0], [%1], 16;\n" :: "r"(s), "l"(g));
}
__device__ __forceinline__ void cp_commit() { asm volatile("cp.async.commit_group;\n"); }

__device__ __forceinline__ void ldm_x4(uint32_t& r0, uint32_t& r1, uint32_t& r2,
                                       uint32_t& r3, uint32_t addr) {
    asm volatile("ldmatrix.sync.aligned.m8n8.x4.shared.b16 {%0,%1,%2,%3}, [%4];"
                 : "=r"(r0), "=r"(r1), "=r"(r2), "=r"(r3) : "r"(addr));
}
__device__ __forceinline__ void mma_f16(float* c, const uint32_t* a, const uint32_t* b) {
    asm volatile(
        "mma.sync.aligned.m16n8k16.row.col.f32.f16.f16.f32 "
        "{%0,%1,%2,%3}, {%4,%5,%6,%7}, {%8,%9}, {%0,%1,%2,%3};"
        : "+f"(c[0]), "+f"(c[1]), "+f"(c[2]), "+f"(c[3])
        : "r"(a[0]), "r"(a[1]), "r"(a[2]), "r"(a[3]), "r"(b[0]), "r"(b[1]));
}

// ---------------- fp16 packing -----------------------------------------------------
// A: out row stride 2K: [hi at c, lo at K+c]  (hi/lo split of fp32, ~22-bit exact)
__global__ __launch_bounds__(256) void pack_a(
    const float* __restrict__ src, __half* __restrict__ dst, int K, int total)
{
    int i = (blockIdx.x * blockDim.x + threadIdx.x) * 2;
    if (i >= total) return;
    float2 v = *(const float2*)(src + i);
    __half h0 = __float2half_rn(v.x);
    __half l0 = __float2half_rn(v.x - __half2float(h0));
    __half h1 = __float2half_rn(v.y);
    __half l1 = __float2half_rn(v.y - __half2float(h1));
    __half2 hh = { h0, h1 };
    __half2 ll = { l0, l1 };
    int r = i / K, c = i - r * K;                 // K even, i even -> same row
    size_t base = (size_t)r * (2 * K) + c;
    *(__half2*)(dst + base)     = hh;
    *(__half2*)(dst + base + K) = ll;
}

// W: plain fp32 -> fp16 convert, same layout
__global__ __launch_bounds__(256) void pack_w(
    const float* __restrict__ src, __half* __restrict__ dst, int total)
{
    int i = (blockIdx.x * blockDim.x + threadIdx.x) * 2;
    if (i >= total) return;
    float2 v = *(const float2*)(src + i);
    __half2 hh = { __float2half_rn(v.x), __float2half_rn(v.y) };
    *(__half2*)(dst + i) = hh;
}

// ---------------- fp16 mma.sync GEMM: C[M,N] = A'[M,2K] @ [W|W][N,2K]^T -----------
// block 128x128, BK=32 fp16, 4-stage cp.async, 8 warps (warp tile 64x32), ldmatrix.
// A row stride K2 = 2K; W row stride KW = K, k-offset wraps mod KW.
// mode 0: C = acc + bias ; mode 1: g = sigmoid(acc+bias); dst = g*Araw + (1-g)*prev
#define SSB   80
#define STGB  (256 * SSB)
#define BOFF  (128 * SSB)
#define NSTG  4
#define GSMEM (NSTG * STGB)

__global__ __launch_bounds__(256, 2) void hf_gemm(
    const __half* __restrict__ A,
    const __half* __restrict__ W,
    const float* __restrict__ bias,
    float* __restrict__ C,
    int Ncols, int K2, int KW, int mode,
    const float* __restrict__ Araw,
    const float* __restrict__ prev,
    float* __restrict__ dst)
{
    extern __shared__ char smem[];
    uint32_t sb;
    asm("{ .reg .u64 t; cvta.to.shared.u64 t, %1; cvt.u32.u64 %0, t; }"
        : "=r"(sb) : "l"(smem));

    const int tid  = threadIdx.x;
    const int warp = tid >> 5;
    const int lane = tid & 31;
    const int bm   = blockIdx.y * 128;
    const int bn   = blockIdx.x * 128;
    const int wm   = (warp & 1) * 64;
    const int wn   = (warp >> 1) * 32;
    const int gid  = lane >> 2;
    const int tig  = lane & 3;

    float acc[4][4][4];
#pragma unroll
    for (int mt = 0; mt < 4; mt++)
#pragma unroll
        for (int nt = 0; nt < 4; nt++)
#pragma unroll
            for (int r = 0; r < 4; r++) acc[mt][nt][r] = 0.f;

    const int nkc = K2 / 32;

    auto issue_loads = [&](int kc) {
        const uint32_t st = sb + (kc & (NSTG - 1)) * STGB;
        const int ka = kc * 32;
        const int kw = (ka < KW) ? ka : (ka - KW);   // W wraps mod KW
#pragma unroll
        for (int j = 0; j < 4; j++) {
            int c   = tid + j * 256;
            int isB = c >> 9;
            int idx = c & 511;
            int row = idx >> 2;
            int q   = idx & 3;
            const __half* gp = isB
                ? (W + (size_t)(bn + row) * KW + kw + q * 8)
                : (A + (size_t)(bm + row) * K2 + ka + q * 8);
            cp16(st + isB * BOFF + row * SSB + q * 16, gp);
        }
        cp_commit();
    };

    issue_loads(0);
    if (nkc > 1) issue_loads(1);
    if (nkc > 2) issue_loads(2);

    for (int kc = 0; kc < nkc; kc++) {
        if (kc + 2 < nkc)      asm volatile("cp.async.wait_group 2;\n" ::: "memory");
        else if (kc + 1 < nkc) asm volatile("cp.async.wait_group 1;\n" ::: "memory");
        else                   asm volatile("cp.async.wait_group 0;\n" ::: "memory");
        __syncthreads();
        if (kc + 3 < nkc) issue_loads(kc + 3);

        const uint32_t st = sb + (kc & (NSTG - 1)) * STGB;
#pragma unroll
        for (int ks = 0; ks < 2; ks++) {
            const int k0b = ks * 32;
            uint32_t a[4][4];
#pragma unroll
            for (int mt = 0; mt < 4; mt++) {
                uint32_t ad = st + (wm + mt * 16 + (lane & 15)) * SSB
                            + ((lane >> 4) * 16) + k0b;
                ldm_x4(a[mt][0], a[mt][1], a[mt][2], a[mt][3], ad);
            }
            uint32_t b[4][2];
#pragma unroll
            for (int np = 0; np < 2; np++) {
                uint32_t bd = st + BOFF
                            + (wn + np * 16 + (lane & 7) + ((lane >> 4) * 8)) * SSB
                            + (((lane >> 3) & 1) * 16) + k0b;
                ldm_x4(b[2 * np][0], b[2 * np][1], b[2 * np + 1][0], b[2 * np + 1][1], bd);
            }
#pragma unroll
            for (int mt = 0; mt < 4; mt++)
#pragma unroll
                for (int nt = 0; nt < 4; nt++)
                    mma_f16(acc[mt][nt], a[mt], b[nt]);
        }
    }

#pragma unroll
    for (int mt = 0; mt < 4; mt++) {
#pragma unroll
        for (int nt = 0; nt < 4; nt++) {
            int r0 = bm + wm + mt * 16 + gid;
            int c0 = bn + wn + nt * 8 + tig * 2;
            float bs0 = bias[c0], bs1 = bias[c0 + 1];
            if (mode == 0) {
                float2 v0 = { acc[mt][nt][0] + bs0, acc[mt][nt][1] + bs1 };
                float2 v1 = { acc[mt][nt][2] + bs0, acc[mt][nt][3] + bs1 };
                *(float2*)(C + (size_t)r0 * Ncols + c0) = v0;
                *(float2*)(C + (size_t)(r0 + 8) * Ncols + c0) = v1;
            } else {
#pragma unroll
                for (int rr = 0; rr < 2; rr++) {
                    int row = r0 + rr * 8;
                    size_t idx = (size_t)row * Ncols + c0;
                    float2 av = *(const float2*)(Araw + idx);
                    float2 pv = *(const float2*)(prev + idx);
                    float g0 = sigmoidf_(acc[mt][nt][rr * 2 + 0] + bs0);
                    float g1 = sigmoidf_(acc[mt][nt][rr * 2 + 1] + bs1);
                    float2 o = { g0 * av.x + (1.f - g0) * pv.x,
                                 g1 * av.y + (1.f - g1) * pv.y };
                    *(float2*)(dst + idx) = o;
                }
            }
        }
    }
}

// ---------------- grid barrier (per direction, 64 blocks) -------------------------
__device__ __forceinline__ void grid_barrier_dir(int dir) {
    __syncthreads();
    if (threadIdx.x == 0) {
        __threadfence();
        unsigned gen = g_barg2[dir];
        unsigned a = atomicAdd(&g_barc2[dir], 1u);
        if (a == 63u) {
            g_barc2[dir] = 0u;
            __threadfence();
            g_barg2[dir] = gen + 1u;
        } else {
            while (g_barg2[dir] == gen) { }
            __threadfence();
        }
    }
    __syncthreads();
}

// ---------------- persistent recurrent kernel v2 (proven R8 version) --------------
#define SM_W4F   16384                // Wq floats (4096 float4)
#define SM_TILE  (64 * 65)            // floats per h tile buffer
#define SMEM_REC ((SM_W4F + 2 * SM_TILE) * sizeof(float))   // 98816 B

__global__ __launch_bounds__(256, 1) void lstm_rec(
    const float* __restrict__ Whh_f, const float* __restrict__ Whh_b,
    const float* __restrict__ init_f, const float* __restrict__ init_b,
    const float* __restrict__ masks,
    float* __restrict__ outbuf,   // [T,B,2H]; this dir writes cols [dir*H, dir*H+H)
    float* __restrict__ hn, float* __restrict__ cn,  // [6,B,H]
    int layer)
{
    extern __shared__ float sm[];
    float4* Wq  = (float4*)sm;            // [512*8] : (k, hid) -> {wi,wf,wg,wo}
    float*  hs0 = sm + SM_W4F;
    float*  hs1 = hs0 + SM_TILE;

    const int dir = blockIdx.x >> 6;
    const int hb  = (blockIdx.x & 63) << 3;
    const float* gbuf = dir ? g_gb : g_gf;
    const float* Whh  = dir ? Whh_b : Whh_f;
    const float* init = dir ? init_b : init_f;       // [2,512]: h0 then c0
    const int tid = threadIdx.x;
    const int hid = tid & 7;
    const int b0  = (tid >> 3) * 2;                  // 2 batches per thread
    const int hg  = hb + hid;

    for (int i = tid; i < 4096; i += 256) {
        int k = i >> 3, hl = i & 7, row = hb + hl;
        Wq[i] = make_float4(Whh[(size_t)row * 512 + k],
                            Whh[(size_t)(512 + row) * 512 + k],
                            Whh[(size_t)(1024 + row) * 512 + k],
                            Whh[(size_t)(1536 + row) * 512 + k]);
    }

    float cst[2], hlast[2];
    cst[0] = cst[1] = init[512 + hg];
    hlast[0] = hlast[1] = 0.f;

    float pg[8], pm[2];
    {
        const int tg = dir ? (TSTEPS - 1) : 0;
        const float* gp = gbuf + (size_t)tg * NB * G4 + hg;
#pragma unroll
        for (int b = 0; b < 2; b++) {
            const float* r = gp + (size_t)(b0 + b) * G4;
            pg[b * 4 + 0] = r[0];    pg[b * 4 + 1] = r[512];
            pg[b * 4 + 2] = r[1024]; pg[b * 4 + 3] = r[1536];
            pm[b] = masks[tg * NB + b0 + b];
        }
    }
    __syncthreads();   // weights visible

    for (int t = 0; t < TSTEPS; ++t) {
        const int tg = dir ? (TSTEPS - 1 - t) : t;
        float ai[2] = { pg[0], pg[4] }, af[2] = { pg[1], pg[5] };
        float ag[2] = { pg[2], pg[6] }, ao[2] = { pg[3], pg[7] };
        const float* hsrc = &g_h[dir][(t + 1) & 1][0];

        float4 ld[4];
        auto ldt = [&](int j) {
            const int k0 = j * 64;
#pragma unroll
            for (int r = 0; r < 4; r++) {
                int flat = tid + r * 256;       // [0,1024)
                int bb = flat >> 4, kq = flat & 15;
                if (t == 0) {
                    ld[r].x = init[k0 + kq * 4 + 0];
                    ld[r].y = init[k0 + kq * 4 + 1];
                    ld[r].z = init[k0 + kq * 4 + 2];
                    ld[r].w = init[k0 + kq * 4 + 3];
                    (void)bb;
                } else {
                    ld[r] = *(const float4*)(hsrc + bb * 512 + k0 + kq * 4);
                }
            }
        };
        auto stt = [&](float* buf) {
#pragma unroll
            for (int r = 0; r < 4; r++) {
                int flat = tid + r * 256;
                int bb = flat >> 4, kq = flat & 15;
                buf[(kq * 4 + 0) * 65 + bb] = ld[r].x;
                buf[(kq * 4 + 1) * 65 + bb] = ld[r].y;
                buf[(kq * 4 + 2) * 65 + bb] = ld[r].z;
                buf[(kq * 4 + 3) * 65 + bb] = ld[r].w;
            }
        };

        ldt(0); stt(hs0); __syncthreads();
        float* bufs[2] = { hs0, hs1 };
#pragma unroll 1
        for (int j = 0; j < 8; j++) {
            if (j < 7) ldt(j + 1);                  // prefetch next tile (LDG in flight)
            const float* cb = bufs[j & 1];
            const float4* wp = Wq + (j * 64) * 8 + hid;
#pragma unroll 16
            for (int kk = 0; kk < 64; kk++) {
                float4 w = wp[kk * 8];
                float h0 = cb[kk * 65 + b0];
                float h1 = cb[kk * 65 + b0 + 1];
                ai[0] += h0 * w.x; af[0] += h0 * w.y; ag[0] += h0 * w.z; ao[0] += h0 * w.w;
                ai[1] += h1 * w.x; af[1] += h1 * w.y; ag[1] += h1 * w.z; ao[1] += h1 * w.w;
            }
            if (j < 7) { stt(bufs[(j + 1) & 1]); __syncthreads(); }
        }

        float* hdst = &g_h[dir][t & 1][0];
        float* od = outbuf + (size_t)tg * NB * D2H + dir * HID + hg;
#pragma unroll
        for (int b = 0; b < 2; b++) {
            float m = pm[b];
            float I  = sigmoidf_(ai[b]);
            float F  = sigmoidf_(af[b]);
            float Gv = tanhf(ag[b]);
            float O  = sigmoidf_(ao[b]);
            float c = (F * cst[b] + I * Gv) * m;
            cst[b] = c;
            float h = O * tanhf(c) * m;
            hlast[b] = h;
            hdst[(b0 + b) * HID + hg] = h;
            od[(size_t)(b0 + b) * D2H] = h;
        }

        if (t + 1 < TSTEPS) {
            const int tn = dir ? (TSTEPS - 2 - t) : (t + 1);
            const float* gp = gbuf + (size_t)tn * NB * G4 + hg;
#pragma unroll
            for (int b = 0; b < 2; b++) {
                const float* r = gp + (size_t)(b0 + b) * G4;
                pg[b * 4 + 0] = r[0];    pg[b * 4 + 1] = r[512];
                pg[b * 4 + 2] = r[1024]; pg[b * 4 + 3] = r[1536];
                pm[b] = masks[tn * NB + b0 + b];
            }
        }
        grid_barrier_dir(dir);
    }

    const int si = layer * 2 + dir;   // h_n order: fh0, bh0, fh1, bh1, fh2, bh2
#pragma unroll
    for (int b = 0; b < 2; b++) {
        hn[(size_t)si * NB * HID + (b0 + b) * HID + hg] = hlast[b];
        cn[(size_t)si * NB * HID + (b0 + b) * HID + hg] = cst[b];
    }
}

// ---------------- host ------------------------------------------------------------
extern "C" void kernel_launch(void* const* d_in, const int* in_sizes, int n_in,
                              void* d_out, int out_size)
{
    const float* x     = (const float*)d_in[0];   // [256,64,512]
    const float* masks = (const float*)d_in[1];   // [256,64,1]
    const float* fWih0 = (const float*)d_in[2];   // [2048,512]
    const float* fWihR = (const float*)d_in[3];   // [2,2048,1024]
    const float* fWhh  = (const float*)d_in[4];   // [3,2048,512]
    const float* fb    = (const float*)d_in[5];   // [3,2048]
    const float* bWih0 = (const float*)d_in[6];
    const float* bWihR = (const float*)d_in[7];
    const float* bWhh  = (const float*)d_in[8];
    const float* bb    = (const float*)d_in[9];
    const float* finit = (const float*)d_in[10];  // [3,2,512]
    const float* binit = (const float*)d_in[11];
    const float* projW = (const float*)d_in[12];  // [2,1024,1024]
    const float* projB = (const float*)d_in[13];  // [2,1024]

    float* out = (float*)d_out;                      // [256,64,1024]
    float* hn  = out + (size_t)MROWS * D2H;          // [6,64,512]
    float* cn  = hn + (size_t)6 * NB * HID;          // [6,64,512]

    float *gf, *gb, *feat0, *feat1, *lstmb;
    __half *Ahf, *Whf;
    cudaGetSymbolAddress((void**)&gf, g_gf);
    cudaGetSymbolAddress((void**)&gb, g_gb);
    cudaGetSymbolAddress((void**)&feat0, g_feat0);
    cudaGetSymbolAddress((void**)&feat1, g_feat1);
    cudaGetSymbolAddress((void**)&lstmb, g_lstm);
    cudaGetSymbolAddress((void**)&Ahf, g_Ahf);
    cudaGetSymbolAddress((void**)&Whf, g_Whf);

    cudaFuncSetAttribute(lstm_rec, cudaFuncAttributeMaxDynamicSharedMemorySize,
                         (int)SMEM_REC);
    cudaFuncSetAttribute(hf_gemm, cudaFuncAttributeMaxDynamicSharedMemorySize,
                         (int)GSMEM);

    dim3 gg(G4 / 128, MROWS / 128);    // gates:  16 x 128
    dim3 gp(D2H / 128, MROWS / 128);   // proj:    8 x 128
    const int CT = 256;

    auto packA = [&](const float* src, int K) {
        int tot = MROWS * K;
        pack_a<<<(tot / 2 + CT - 1) / CT, CT>>>(src, Ahf, K, tot);
    };
    auto packW = [&](const float* src, int N, int K) {
        int tot = N * K;
        pack_w<<<(tot / 2 + CT - 1) / CT, CT>>>(src, Whf, tot);
    };

    // ---- layer 0 (K=512 -> K2=1024) ----
    packA(x, 512);
    packW(fWih0, G4, 512);
    hf_gemm<<<gg, 256, GSMEM>>>(Ahf, Whf, fb, gf, G4, 1024, 512, 0,
                                nullptr, nullptr, nullptr);
    packW(bWih0, G4, 512);
    hf_gemm<<<gg, 256, GSMEM>>>(Ahf, Whf, bb, gb, G4, 1024, 512, 0,
                                nullptr, nullptr, nullptr);
    lstm_rec<<<128, 256, SMEM_REC>>>(fWhh, bWhh, finit, binit, masks,
                                     feat0, hn, cn, 0);

    // ---- layer 1 (K=1024 -> K2=2048) ----
    packA(feat0, 1024);
    packW(fWihR, G4, 1024);
    hf_gemm<<<gg, 256, GSMEM>>>(Ahf, Whf, fb + 2048, gf, G4, 2048, 1024, 0,
                                nullptr, nullptr, nullptr);
    packW(bWihR, G4, 1024);
    hf_gemm<<<gg, 256, GSMEM>>>(Ahf, Whf, bb + 2048, gb, G4, 2048, 1024, 0,
                                nullptr, nullptr, nullptr);
    lstm_rec<<<128, 256, SMEM_REC>>>(fWhh + (size_t)2048 * 512,
                                     bWhh + (size_t)2048 * 512,
                                     finit + 1024, binit + 1024, masks,
                                     lstmb, hn, cn, 1);
    packA(lstmb, 1024);
    packW(projW, D2H, 1024);
    hf_gemm<<<gp, 256, GSMEM>>>(Ahf, Whf, projB, feat1, D2H, 2048, 1024, 1,
                                lstmb, feat0, feat1);

    // ---- layer 2 (K=1024 -> K2=2048) ----
    packA(feat1, 1024);
    packW(fWihR + (size_t)2048 * 1024, G4, 1024);
    hf_gemm<<<gg, 256, GSMEM>>>(Ahf, Whf, fb + 4096, gf, G4, 2048, 1024, 0,
                                nullptr, nullptr, nullptr);
    packW(bWihR + (size_t)2048 * 1024, G4, 1024);
    hf_gemm<<<gg, 256, GSMEM>>>(Ahf, Whf, bb + 4096, gb, G4, 2048, 1024, 0,
                                nullptr, nullptr, nullptr);
    lstm_rec<<<128, 256, SMEM_REC>>>(fWhh + (size_t)2 * 2048 * 512,
                                     bWhh + (size_t)2 * 2048 * 512,
                                     finit + 2048, binit + 2048, masks,
                                     lstmb, hn, cn, 2);
    packA(lstmb, 1024);
    packW(projW + (size_t)1024 * 1024, D2H, 1024);
    hf_gemm<<<gp, 256, GSMEM>>>(Ahf, Whf, projB + 1024, out, D2H, 2048, 1024, 1,
                                lstmb, feat1, out);
}